// round 1
// baseline (speedup 1.0000x reference)
#include <cuda_runtime.h>
#include <cstdint>

namespace {

constexpr int S_LEN = 2048;
constexpr int DD    = 64;     // head dim
constexpr int BM    = 64;     // q rows per tile
constexpr int BN    = 64;     // k rows per tile
constexpr int NT    = 256;    // threads per CTA
constexpr int QSTR  = 68;     // Q smem row stride (floats), padded
constexpr int SMEM_FLOATS = BM*QSTR + 2*BN*DD + 2*BN*DD + BM*BN;
constexpr int SMEM_BYTES  = SMEM_FLOATS * 4;   // 99328 B

typedef unsigned long long u64;

__device__ __forceinline__ u64 pk2(float lo, float hi){
  u64 r; asm("mov.b64 %0,{%1,%2};" : "=l"(r) : "f"(lo), "f"(hi)); return r;
}
__device__ __forceinline__ void upk2(u64 v, float& lo, float& hi){
  asm("mov.b64 {%0,%1},%2;" : "=f"(lo), "=f"(hi) : "l"(v));
}
// packed fp32x2 FMA: d = a*b + d  (2x fp32 FMA throughput on sm_103a)
__device__ __forceinline__ void fma2(u64& d, u64 a, u64 b){
  asm("fma.rn.f32x2 %0,%1,%2,%0;" : "+l"(d) : "l"(a), "l"(b));
}
__device__ __forceinline__ void mul2(u64& d, u64 a){
  asm("mul.rn.f32x2 %0,%0,%1;" : "+l"(d) : "l"(a));
}

__device__ __forceinline__ void cpa16(float* smem, const float* gmem){
  uint32_t s = (uint32_t)__cvta_generic_to_shared(smem);
  asm volatile("cp.async.cg.shared.global [%0],[%1],16;" :: "r"(s), "l"(gmem));
}
__device__ __forceinline__ void cp_commit(){ asm volatile("cp.async.commit_group;"); }
__device__ __forceinline__ void cp_wait0(){ asm volatile("cp.async.wait_group 0;" ::: "memory"); }

// Causal flash attention, fp32, no 1/sqrt(d) scaling.
// Grid: B*16 CTAs. CTA (b, p) processes q-tiles j = 31-p and j = p
// (work pairing: (32-p) + (p+1) = 33 k-iterations per CTA -> perfectly
//  balanced single wave of 128 CTAs on 148 SMs).
// Thread map (256 thr): ty = tid/16, tx = tid%16.
//   S micro-tile: rows {4ty..4ty+3} x cols {tx+16*jj, jj=0..3}
//   O micro-tile: rows {4ty..4ty+3} x dcols {4tx..4tx+3}
// K/V smem: row-major 64 floats/row, float4-index XOR swizzle f4' = f4 ^ (row&7)
//   -> conflict-free LDS.128 for both K (16 consecutive rows / warp-half) and
//      V (one row spread across 16 lanes).
__global__ void __launch_bounds__(NT, 1)
attn_fa_kernel(const float* __restrict__ Q, const float* __restrict__ K,
               const float* __restrict__ V, float* __restrict__ O)
{
  extern __shared__ float sm[];
  float* Qs  = sm;                    // BM x QSTR
  float* Ksm = sm + BM*QSTR;          // 2 x (BN x 64), swizzled
  float* Vsm = Ksm + 2*BN*DD;         // 2 x (BN x 64), swizzled
  float* Ps  = Vsm + 2*BN*DD;         // BM x BN

  const int tid = threadIdx.x;
  const int tx  = tid & 15;
  const int ty  = tid >> 4;
  const int b   = blockIdx.x >> 4;
  const int pr  = blockIdx.x & 15;

  const float* Qb = Q + (size_t)b * S_LEN * DD;
  const float* Kb = K + (size_t)b * S_LEN * DD;
  const float* Vb = V + (size_t)b * S_LEN * DD;
  float*       Ob = O + (size_t)b * S_LEN * DD;

  const int ksw = tx & 7;   // K-read swizzle term: (tx+16jj)&7 == tx&7

  #pragma unroll 1
  for (int half = 0; half < 2; ++half){
    const int j  = half ? pr : (31 - pr);   // big tile first
    const int q0 = j * BM;

    __syncthreads();   // smem reuse across halves

    // ---- load Q tile (global -> smem), coalesced float4
    #pragma unroll
    for (int kk = 0; kk < (BM*DD/4)/NT; ++kk){
      int cid = tid + NT*kk;
      int r = cid >> 4, f4 = cid & 15;
      float4 qv = *reinterpret_cast<const float4*>(Qb + (size_t)(q0 + r)*DD + f4*4);
      *reinterpret_cast<float4*>(Qs + r*QSTR + f4*4) = qv;
    }

    // ---- kick off K/V tile 0 into buffer 0 (cp.async, swizzled dst)
    #pragma unroll
    for (int kk = 0; kk < 4; ++kk){
      int cid = tid + NT*kk;
      int r = cid >> 4, f4 = cid & 15, f4s = f4 ^ (r & 7);
      cpa16(Ksm + r*DD + f4s*4, Kb + (size_t)r*DD + f4*4);
      cpa16(Vsm + r*DD + f4s*4, Vb + (size_t)r*DD + f4*4);
    }
    cp_commit();

    // ---- accumulator state
    u64   o2[4][2];
    float m[4], l[4];
    #pragma unroll
    for (int i = 0; i < 4; ++i){ m[i] = -1e30f; l[i] = 0.f; o2[i][0] = 0ull; o2[i][1] = 0ull; }

    #pragma unroll 1
    for (int t = 0; t <= j; ++t){
      cp_wait0();
      __syncthreads();   // tile t visible; all threads done with previous iteration
      const float* Kt = Ksm + (t & 1)*BN*DD;
      const float* Vt = Vsm + (t & 1)*BN*DD;

      // prefetch tile t+1 into the other buffer (safe: everyone passed the sync)
      if (t < j){
        const float* Kg = Kb + (size_t)(t+1)*BN*DD;
        const float* Vg = Vb + (size_t)(t+1)*BN*DD;
        float* Kd = Ksm + ((t+1) & 1)*BN*DD;
        float* Vd = Vsm + ((t+1) & 1)*BN*DD;
        #pragma unroll
        for (int kk = 0; kk < 4; ++kk){
          int cid = tid + NT*kk;
          int r = cid >> 4, f4 = cid & 15, f4s = f4 ^ (r & 7);
          cpa16(Kd + r*DD + f4s*4, Kg + (size_t)r*DD + f4*4);
          cpa16(Vd + r*DD + f4s*4, Vg + (size_t)r*DD + f4*4);
        }
        cp_commit();
      }

      // ---- S = Q * K^T  (packed f32x2 FMA along d)
      u64 acc[4][4];
      #pragma unroll
      for (int i = 0; i < 4; ++i)
        #pragma unroll
        for (int jj = 0; jj < 4; ++jj) acc[i][jj] = 0ull;

      #pragma unroll
      for (int d4 = 0; d4 < 16; ++d4){
        u64 qa[4][2], kb[4][2];
        #pragma unroll
        for (int i = 0; i < 4; ++i){
          const u64* p = reinterpret_cast<const u64*>(Qs + (4*ty + i)*QSTR + d4*4);
          qa[i][0] = p[0]; qa[i][1] = p[1];
        }
        const int f4s = d4 ^ ksw;
        #pragma unroll
        for (int jj = 0; jj < 4; ++jj){
          const u64* p = reinterpret_cast<const u64*>(Kt + (tx + 16*jj)*DD + f4s*4);
          kb[jj][0] = p[0]; kb[jj][1] = p[1];
        }
        #pragma unroll
        for (int i = 0; i < 4; ++i)
          #pragma unroll
          for (int jj = 0; jj < 4; ++jj){
            fma2(acc[i][jj], qa[i][0], kb[jj][0]);
            fma2(acc[i][jj], qa[i][1], kb[jj][1]);
          }
      }

      float s[4][4];
      #pragma unroll
      for (int i = 0; i < 4; ++i)
        #pragma unroll
        for (int jj = 0; jj < 4; ++jj){
          float lo, hi; upk2(acc[i][jj], lo, hi);
          s[i][jj] = lo + hi;
        }

      // ---- causal mask (only the diagonal tile needs it)
      if (t == j){
        #pragma unroll
        for (int i = 0; i < 4; ++i){
          const int qg = q0 + 4*ty + i;
          #pragma unroll
          for (int jj = 0; jj < 4; ++jj){
            const int cg = t*BN + tx + 16*jj;
            if (cg > qg) s[i][jj] = -1e30f;
          }
        }
      }

      // ---- online softmax (row stats across 16 tx-lanes via shfl.xor)
      float p[4][4];
      #pragma unroll
      for (int i = 0; i < 4; ++i){
        float mi = fmaxf(fmaxf(s[i][0], s[i][1]), fmaxf(s[i][2], s[i][3]));
        mi = fmaxf(mi, __shfl_xor_sync(0xffffffffu, mi, 1));
        mi = fmaxf(mi, __shfl_xor_sync(0xffffffffu, mi, 2));
        mi = fmaxf(mi, __shfl_xor_sync(0xffffffffu, mi, 4));
        mi = fmaxf(mi, __shfl_xor_sync(0xffffffffu, mi, 8));
        const float mn = fmaxf(m[i], mi);
        const float al = __expf(m[i] - mn);   // m init -1e30 -> al=0 first time
        m[i] = mn;
        float rs = 0.f;
        #pragma unroll
        for (int jj = 0; jj < 4; ++jj){
          p[i][jj] = __expf(s[i][jj] - mn);   // masked -> exp(-huge) = 0
          rs += p[i][jj];
        }
        rs += __shfl_xor_sync(0xffffffffu, rs, 1);
        rs += __shfl_xor_sync(0xffffffffu, rs, 2);
        rs += __shfl_xor_sync(0xffffffffu, rs, 4);
        rs += __shfl_xor_sync(0xffffffffu, rs, 8);
        l[i] = l[i]*al + rs;
        const u64 a2 = pk2(al, al);
        mul2(o2[i][0], a2);
        mul2(o2[i][1], a2);
      }

      // ---- stage P to smem for the PV contraction
      #pragma unroll
      for (int i = 0; i < 4; ++i)
        #pragma unroll
        for (int jj = 0; jj < 4; ++jj)
          Ps[(4*ty + i)*BN + tx + 16*jj] = p[i][jj];

      __syncthreads();

      // ---- O += P * V  (packed f32x2 along d-columns)
      #pragma unroll
      for (int c4 = 0; c4 < 16; ++c4){
        float pj[4][4];
        #pragma unroll
        for (int i = 0; i < 4; ++i){
          float4 pv = *reinterpret_cast<const float4*>(Ps + (4*ty + i)*BN + c4*4);
          pj[i][0] = pv.x; pj[i][1] = pv.y; pj[i][2] = pv.z; pj[i][3] = pv.w;
        }
        u64 vv[4][2];
        #pragma unroll
        for (int cc = 0; cc < 4; ++cc){
          const int c = 4*c4 + cc;
          const u64* vp = reinterpret_cast<const u64*>(Vt + c*DD + (tx ^ (c & 7))*4);
          vv[cc][0] = vp[0]; vv[cc][1] = vp[1];
        }
        #pragma unroll
        for (int cc = 0; cc < 4; ++cc)
          #pragma unroll
          for (int i = 0; i < 4; ++i){
            const u64 pp = pk2(pj[i][cc], pj[i][cc]);
            fma2(o2[i][0], pp, vv[cc][0]);
            fma2(o2[i][1], pp, vv[cc][1]);
          }
      }
    } // k-tile loop

    // ---- epilogue: O /= l, write float4 rows
    #pragma unroll
    for (int i = 0; i < 4; ++i){
      const float inv = 1.0f / l[i];
      float a, bb, c, d;
      upk2(o2[i][0], a, bb);
      upk2(o2[i][1], c, d);
      float4 ov = make_float4(a*inv, bb*inv, c*inv, d*inv);
      *reinterpret_cast<float4*>(Ob + (size_t)(q0 + 4*ty + i)*DD + tx*4) = ov;
    }
  } // half
}

} // anonymous namespace

extern "C" void kernel_launch(void* const* d_in, const int* in_sizes, int n_in,
                              void* d_out, int out_size)
{
  const float* q = (const float*)d_in[0];
  const float* k = (const float*)d_in[1];
  const float* v = (const float*)d_in[2];
  float* o = (float*)d_out;

  const int B = in_sizes[0] / (S_LEN * DD);   // 8 for this problem

  cudaFuncSetAttribute(attn_fa_kernel,
                       cudaFuncAttributeMaxDynamicSharedMemorySize, SMEM_BYTES);
  attn_fa_kernel<<<B * 16, NT, SMEM_BYTES>>>(q, k, v, o);
}